// round 13
// baseline (speedup 1.0000x reference)
#include <cuda_runtime.h>
#include <cuda_fp16.h>

// CapsuleLayer dynamic routing, round 12: two kernels, G=8.
// x: [B=64, Cin=8, R=800] fp32 ; W: [NC=128, R=800, Cin=8, O=16] fp32
// out: [B=64, O=16, NC=128] fp32
//
// R12 = R11 structure (batched loads, fused pass-0, 2 routing passes) +
//   (1) xT scratch in fp32: kills the 64 F2F converts per phase-1
//       group-iter (17% of phase-1 issue) while KEEPING the batched 4-g
//       load shape that R10 broke (R10's regression was serialization,
//       not fp32). Also removes x-quantization error.
//   (2) #pragma unroll 2 on the phase-2 r-loop (long per-iter dependency
//       chain: LDS->dot->SHFL->exp->FMA; 2x ILP, registers are free).

namespace {

constexpr int kB    = 64;
constexpr int kCin  = 8;
constexpr int kR    = 800;
constexpr int kNC   = 128;
constexpr int kO    = 16;
constexpr int kG    = 8;
constexpr int kT    = 512;
constexpr int kBPC  = kB / kG;        // 8 CTAs per capsule
constexpr int kWRow = kCin * kO;

struct Smem {
    __half2 prio[kG][kR][kO / 2];     // 204800 B
    float   sred[kG][16][kO];         //   8192 B
    float   zred[kG][2];              //     64 B
    float   v[kG][kO];                //    512 B
};

// exp(x) entirely on fma/alu pipes. Valid for |x| < ~88 (inputs bounded ~50).
__device__ __forceinline__ float fast_exp(float x) {
    const float t  = fmaf(x, 1.44269504f, 12582912.0f);
    const float fi = t - 12582912.0f;
    const float f  = fmaf(x, 1.44269504f, -fi);
    float p = 1.54035304e-4f;
    p = fmaf(p, f, 1.33335581e-3f);
    p = fmaf(p, f, 9.61812911e-3f);
    p = fmaf(p, f, 5.55041087e-2f);
    p = fmaf(p, f, 2.40226507e-1f);
    p = fmaf(p, f, 6.93147182e-1f);
    p = fmaf(p, f, 1.0f);
    const int ii = __float_as_int(t) - 0x4B400000;
    return __int_as_float(__float_as_int(p) + (ii << 23));
}

} // namespace

// fp32 transposed x: xT[b][r][i], 32B rows. 1.6384 MB scratch.
__device__ __align__(128) static float d_xT[kB * kR * kCin];

__global__ void transpose_x_kernel(const float* __restrict__ x) {
    const int id = blockIdx.x * blockDim.x + threadIdx.x;   // one (b, r) each
    if (id >= kB * kR) return;
    const int b = id / kR;
    const int r = id - b * kR;
    const float* src = x + (size_t)b * (kCin * kR) + r;
    float4 v0, v1;
    v0.x = src[0 * kR]; v0.y = src[1 * kR]; v0.z = src[2 * kR]; v0.w = src[3 * kR];
    v1.x = src[4 * kR]; v1.y = src[5 * kR]; v1.z = src[6 * kR]; v1.w = src[7 * kR];
    float4* dst = reinterpret_cast<float4*>(&d_xT[(size_t)id * kCin]);
    dst[0] = v0;
    dst[1] = v1;
}

__global__ __launch_bounds__(kT, 1)
void caps_route_kernel(const float* __restrict__ W,
                       float* __restrict__ out) {
    extern __shared__ char smem_raw[];
    Smem* S = reinterpret_cast<Smem*>(smem_raw);

    const int t    = threadIdx.x;
    const int lane = t & 31;
    const int warp = t >> 5;
    const int c    = blockIdx.x / kBPC;
    const int b0   = (blockIdx.x % kBPC) * kG;
    const float* Wc = W + (size_t)c * (kR * kWRow);
    const float* xT = d_xT + (size_t)b0 * (kR * kCin);

    // ---- phase 1: priors + fused uniform (pass-0) sums ----
    // lane = (rr:3 | oq:2). W held in regs per group; g in two 4-g halves,
    // each half's 8 x-LDGs batched (MLP preserved).
    {
        const int oq = lane & 3;
        const int rr = lane >> 2;
        float ss[kG][4];
        #pragma unroll
        for (int g = 0; g < kG; g++)
            #pragma unroll
            for (int j = 0; j < 4; j++) ss[g][j] = 0.f;

        for (int grp = warp; grp < kR / 8; grp += kT / 32) {
            const int r = grp * 8 + rr;
            const float4* wr = reinterpret_cast<const float4*>(Wc + (size_t)r * kWRow) + oq;
            float4 w[kCin];
            #pragma unroll
            for (int i = 0; i < kCin; i++) w[i] = __ldg(wr + i * 4);

            #pragma unroll
            for (int gh = 0; gh < 2; gh++) {
                float4 xa[4][2];
                #pragma unroll
                for (int gg = 0; gg < 4; gg++) {
                    const float4* xp = reinterpret_cast<const float4*>(
                        xT + ((size_t)(gh * 4 + gg) * kR + r) * kCin);
                    xa[gg][0] = __ldg(xp);
                    xa[gg][1] = __ldg(xp + 1);
                }
                #pragma unroll
                for (int gg = 0; gg < 4; gg++) {
                    const int g = gh * 4 + gg;
                    const float xv[8] = {xa[gg][0].x, xa[gg][0].y, xa[gg][0].z, xa[gg][0].w,
                                         xa[gg][1].x, xa[gg][1].y, xa[gg][1].z, xa[gg][1].w};
                    float4 acc = make_float4(0.f, 0.f, 0.f, 0.f);
                    #pragma unroll
                    for (int i = 0; i < kCin; i++) {
                        acc.x = fmaf(w[i].x, xv[i], acc.x);
                        acc.y = fmaf(w[i].y, xv[i], acc.y);
                        acc.z = fmaf(w[i].z, xv[i], acc.z);
                        acc.w = fmaf(w[i].w, xv[i], acc.w);
                    }
                    union { __half2 h[2]; uint2 u; } pv;
                    pv.h[0] = __floats2half2_rn(acc.x, acc.y);
                    pv.h[1] = __floats2half2_rn(acc.z, acc.w);
                    *reinterpret_cast<uint2*>(&S->prio[g][r][oq * 2]) = pv.u;
                    ss[g][0] += acc.x; ss[g][1] += acc.y;
                    ss[g][2] += acc.z; ss[g][3] += acc.w;
                }
            }
        }
        // reduce ss over rr (lane bits 2..4); lanes rr==0 store per-warp partials
        #pragma unroll
        for (int s = 4; s <= 16; s <<= 1)
            #pragma unroll
            for (int g = 0; g < kG; g++)
                #pragma unroll
                for (int j = 0; j < 4; j++)
                    ss[g][j] += __shfl_xor_sync(0xffffffffu, ss[g][j], s);
        if (rr == 0) {
            #pragma unroll
            for (int g = 0; g < kG; g++)
                *reinterpret_cast<float4*>(&S->sred[g][warp][oq * 4]) =
                    make_float4(ss[g][0], ss[g][1], ss[g][2], ss[g][3]);
        }
    }
    __syncthreads();

    // ---- pass-0 finalize: v0 = squash(sum / R), one warp per g ----
    if (warp < kG && lane < 16) {
        float s = 0.f;
        #pragma unroll
        for (int w = 0; w < 16; w++) s += S->sred[warp][w][lane];
        s *= (1.f / kR);
        float sq = s * s;
        #pragma unroll
        for (int off = 8; off; off >>= 1)
            sq += __shfl_xor_sync(0x0000ffffu, sq, off);
        const float coef = sqrtf(sq) / (1.f + sq);
        S->v[warp][lane] = s * coef;
    }
    __syncthreads();

    // ---- routing: 2 exp-weighted passes over priors ----
    // 2 warps per g: gw = warp>>1, wl = warp&1. lane = (r-slot:4 | ho:1).
    const int gw = warp >> 1;
    const int wl = warp & 1;
    const int ho = lane & 1;
    const int rs = wl * 16 + (lane >> 1);   // 0..31, stride 32 over r

    #pragma unroll
    for (int pass = 0; pass < 2; pass++) {
        const bool last = (pass == 1);

        float vv[8];
        #pragma unroll
        for (int j = 0; j < 8; j++) vv[j] = S->v[gw][ho * 8 + j];

        float z = 0.f, sa[8];
        #pragma unroll
        for (int j = 0; j < 8; j++) sa[j] = 0.f;

        #pragma unroll 2
        for (int r = rs; r < kR; r += 32) {
            union { uint4 u; __half2 h[4]; } cv;
            cv.u = *reinterpret_cast<const uint4*>(&S->prio[gw][r][ho * 4]);
            float p[8];
            #pragma unroll
            for (int k = 0; k < 4; k++) {
                const float2 pf = __half22float2(cv.h[k]);
                p[2 * k] = pf.x; p[2 * k + 1] = pf.y;
            }
            float dh = 0.f;
            #pragma unroll
            for (int j = 0; j < 8; j++) dh = fmaf(p[j], vv[j], dh);
            const float d = dh + __shfl_xor_sync(0xffffffffu, dh, 1);
            const float e = fast_exp(d);        // logits bounded: |d| < ~50
            z += e;
            #pragma unroll
            for (int j = 0; j < 8; j++) sa[j] = fmaf(e, p[j], sa[j]);
        }
        // butterfly over same-parity lanes
        #pragma unroll
        for (int s = 16; s >= 2; s >>= 1) {
            z += __shfl_xor_sync(0xffffffffu, z, s);
            #pragma unroll
            for (int j = 0; j < 8; j++)
                sa[j] += __shfl_xor_sync(0xffffffffu, sa[j], s);
        }
        if (lane < 2) {
            #pragma unroll
            for (int j = 0; j < 8; j++)
                S->sred[gw][wl][lane * 8 + j] = sa[j];
            if (lane == 0) S->zred[gw][wl] = z;
        }
        __syncthreads();

        // finalize + squash: one warp per g
        if (warp < kG && lane < 16) {
            const int g = warp;
            const float Z   = S->zred[g][0] + S->zred[g][1];
            const float num = S->sred[g][0][lane] + S->sred[g][1][lane];
            const float s = num / Z;
            float sq = s * s;
            #pragma unroll
            for (int off = 8; off; off >>= 1)
                sq += __shfl_xor_sync(0x0000ffffu, sq, off);
            const float coef = sqrtf(sq) / (1.f + sq);
            const float vnew = s * coef;
            if (last) {
                out[(size_t)(b0 + g) * (kO * kNC) + (size_t)lane * kNC + c] = vnew;
            } else {
                S->v[g][lane] += vnew;              // vacc = v0 + v1 (linearity)
            }
        }
        if (!last) __syncthreads();
    }
}

extern "C" void kernel_launch(void* const* d_in, const int* in_sizes, int n_in,
                              void* d_out, int out_size) {
    const float* x = (const float*)d_in[0];            // [64, 8, 800]
    const float* W = (const float*)d_in[1];            // [128, 800, 8, 16]
    float* out = (float*)d_out;                        // [64, 16, 128]

    transpose_x_kernel<<<(kB * kR + kT - 1) / kT, kT>>>(x);

    static_assert(sizeof(Smem) <= 227 * 1024, "smem budget");
    cudaFuncSetAttribute(caps_route_kernel,
                         cudaFuncAttributeMaxDynamicSharedMemorySize,
                         (int)sizeof(Smem));
    caps_route_kernel<<<kNC * kBPC, kT, sizeof(Smem)>>>(W, out);
}

// round 14
// speedup vs baseline: 1.1282x; 1.1282x over previous
#include <cuda_runtime.h>
#include <cuda_fp16.h>

// CapsuleLayer dynamic routing, round 13: two kernels, G=8.
// x: [B=64, Cin=8, R=800] fp32 ; W: [NC=128, R=800, Cin=8, O=16] fp32
// out: [B=64, O=16, NC=128] fp32
//
// R13 = R11 EXACTLY (fp16 xT, batched 4-g loads, fused pass-0; the proven
// 106.6us configuration — R12's fp32 xT blew the 128-reg ceiling and
// spilled) + the one safe piece of R12: #pragma unroll 2 on the phase-2
// r-loop (long serial chain LDS->dot->SHFL->exp->FMA; phase 2 has ~90
// regs of headroom so this cannot disturb phase-1 allocation).

namespace {

constexpr int kB    = 64;
constexpr int kCin  = 8;
constexpr int kR    = 800;
constexpr int kNC   = 128;
constexpr int kO    = 16;
constexpr int kG    = 8;
constexpr int kT    = 512;
constexpr int kBPC  = kB / kG;        // 8 CTAs per capsule
constexpr int kWRow = kCin * kO;

struct Smem {
    __half2 prio[kG][kR][kO / 2];     // 204800 B
    float   sred[kG][16][kO];         //   8192 B
    float   zred[kG][2];              //     64 B
    float   v[kG][kO];                //    512 B
};

// exp(x) entirely on fma/alu pipes. Valid for |x| < ~88 (inputs bounded ~50).
__device__ __forceinline__ float fast_exp(float x) {
    const float t  = fmaf(x, 1.44269504f, 12582912.0f);
    const float fi = t - 12582912.0f;
    const float f  = fmaf(x, 1.44269504f, -fi);
    float p = 1.54035304e-4f;
    p = fmaf(p, f, 1.33335581e-3f);
    p = fmaf(p, f, 9.61812911e-3f);
    p = fmaf(p, f, 5.55041087e-2f);
    p = fmaf(p, f, 2.40226507e-1f);
    p = fmaf(p, f, 6.93147182e-1f);
    p = fmaf(p, f, 1.0f);
    const int ii = __float_as_int(t) - 0x4B400000;
    return __int_as_float(__float_as_int(p) + (ii << 23));
}

} // namespace

// fp16 transposed x: xT[b][r][i], 16B rows. 819200 B scratch.
__device__ __align__(128) static __half d_xT[kB * kR * kCin];

__global__ void transpose_x_kernel(const float* __restrict__ x) {
    const int id = blockIdx.x * blockDim.x + threadIdx.x;   // one (b, r) each
    if (id >= kB * kR) return;
    const int b = id / kR;
    const int r = id - b * kR;
    const float* src = x + (size_t)b * (kCin * kR) + r;
    union { __half2 h[4]; uint4 u; } cv;
    #pragma unroll
    for (int k = 0; k < 4; k++)
        cv.h[k] = __floats2half2_rn(src[(2 * k) * kR], src[(2 * k + 1) * kR]);
    *reinterpret_cast<uint4*>(&d_xT[(size_t)id * kCin]) = cv.u;
}

__global__ __launch_bounds__(kT, 1)
void caps_route_kernel(const float* __restrict__ W,
                       float* __restrict__ out) {
    extern __shared__ char smem_raw[];
    Smem* S = reinterpret_cast<Smem*>(smem_raw);

    const int t    = threadIdx.x;
    const int lane = t & 31;
    const int warp = t >> 5;
    const int c    = blockIdx.x / kBPC;
    const int b0   = (blockIdx.x % kBPC) * kG;
    const float* Wc = W + (size_t)c * (kR * kWRow);
    const __half* xT = d_xT + (size_t)b0 * (kR * kCin);

    // ---- phase 1: priors + fused uniform (pass-0) sums ----
    // lane = (rr:3 | oq:2). W held in regs per group; g in two 4-g halves.
    {
        const int oq = lane & 3;
        const int rr = lane >> 2;
        float ss[kG][4];
        #pragma unroll
        for (int g = 0; g < kG; g++)
            #pragma unroll
            for (int j = 0; j < 4; j++) ss[g][j] = 0.f;

        for (int grp = warp; grp < kR / 8; grp += kT / 32) {
            const int r = grp * 8 + rr;
            const float4* wr = reinterpret_cast<const float4*>(Wc + (size_t)r * kWRow) + oq;
            float4 w[kCin];
            #pragma unroll
            for (int i = 0; i < kCin; i++) w[i] = __ldg(wr + i * 4);

            #pragma unroll
            for (int gh = 0; gh < 2; gh++) {
                union { uint4 u; __half2 h[4]; } xa[4];
                #pragma unroll
                for (int gg = 0; gg < 4; gg++)
                    xa[gg].u = *reinterpret_cast<const uint4*>(
                        xT + ((size_t)(gh * 4 + gg) * kR + r) * kCin);

                #pragma unroll
                for (int gg = 0; gg < 4; gg++) {
                    const int g = gh * 4 + gg;
                    float xv[8];
                    #pragma unroll
                    for (int k = 0; k < 4; k++) {
                        const float2 f = __half22float2(xa[gg].h[k]);
                        xv[2 * k] = f.x; xv[2 * k + 1] = f.y;
                    }
                    float4 acc = make_float4(0.f, 0.f, 0.f, 0.f);
                    #pragma unroll
                    for (int i = 0; i < kCin; i++) {
                        acc.x = fmaf(w[i].x, xv[i], acc.x);
                        acc.y = fmaf(w[i].y, xv[i], acc.y);
                        acc.z = fmaf(w[i].z, xv[i], acc.z);
                        acc.w = fmaf(w[i].w, xv[i], acc.w);
                    }
                    union { __half2 h[2]; uint2 u; } pv;
                    pv.h[0] = __floats2half2_rn(acc.x, acc.y);
                    pv.h[1] = __floats2half2_rn(acc.z, acc.w);
                    *reinterpret_cast<uint2*>(&S->prio[g][r][oq * 2]) = pv.u;
                    ss[g][0] += acc.x; ss[g][1] += acc.y;
                    ss[g][2] += acc.z; ss[g][3] += acc.w;
                }
            }
        }
        // reduce ss over rr (lane bits 2..4); lanes rr==0 store per-warp partials
        #pragma unroll
        for (int s = 4; s <= 16; s <<= 1)
            #pragma unroll
            for (int g = 0; g < kG; g++)
                #pragma unroll
                for (int j = 0; j < 4; j++)
                    ss[g][j] += __shfl_xor_sync(0xffffffffu, ss[g][j], s);
        if (rr == 0) {
            #pragma unroll
            for (int g = 0; g < kG; g++)
                *reinterpret_cast<float4*>(&S->sred[g][warp][oq * 4]) =
                    make_float4(ss[g][0], ss[g][1], ss[g][2], ss[g][3]);
        }
    }
    __syncthreads();

    // ---- pass-0 finalize: v0 = squash(sum / R), one warp per g ----
    if (warp < kG && lane < 16) {
        float s = 0.f;
        #pragma unroll
        for (int w = 0; w < 16; w++) s += S->sred[warp][w][lane];
        s *= (1.f / kR);
        float sq = s * s;
        #pragma unroll
        for (int off = 8; off; off >>= 1)
            sq += __shfl_xor_sync(0x0000ffffu, sq, off);
        const float coef = sqrtf(sq) / (1.f + sq);
        S->v[warp][lane] = s * coef;
    }
    __syncthreads();

    // ---- routing: 2 exp-weighted passes over priors ----
    // 2 warps per g: gw = warp>>1, wl = warp&1. lane = (r-slot:4 | ho:1).
    const int gw = warp >> 1;
    const int wl = warp & 1;
    const int ho = lane & 1;
    const int rs = wl * 16 + (lane >> 1);   // 0..31, stride 32 over r

    #pragma unroll
    for (int pass = 0; pass < 2; pass++) {
        const bool last = (pass == 1);

        float vv[8];
        #pragma unroll
        for (int j = 0; j < 8; j++) vv[j] = S->v[gw][ho * 8 + j];

        float z = 0.f, sa[8];
        #pragma unroll
        for (int j = 0; j < 8; j++) sa[j] = 0.f;

        #pragma unroll 2
        for (int r = rs; r < kR; r += 32) {
            union { uint4 u; __half2 h[4]; } cv;
            cv.u = *reinterpret_cast<const uint4*>(&S->prio[gw][r][ho * 4]);
            float p[8];
            #pragma unroll
            for (int k = 0; k < 4; k++) {
                const float2 pf = __half22float2(cv.h[k]);
                p[2 * k] = pf.x; p[2 * k + 1] = pf.y;
            }
            float dh = 0.f;
            #pragma unroll
            for (int j = 0; j < 8; j++) dh = fmaf(p[j], vv[j], dh);
            const float d = dh + __shfl_xor_sync(0xffffffffu, dh, 1);
            const float e = fast_exp(d);        // logits bounded: |d| < ~50
            z += e;
            #pragma unroll
            for (int j = 0; j < 8; j++) sa[j] = fmaf(e, p[j], sa[j]);
        }
        // butterfly over same-parity lanes
        #pragma unroll
        for (int s = 16; s >= 2; s >>= 1) {
            z += __shfl_xor_sync(0xffffffffu, z, s);
            #pragma unroll
            for (int j = 0; j < 8; j++)
                sa[j] += __shfl_xor_sync(0xffffffffu, sa[j], s);
        }
        if (lane < 2) {
            #pragma unroll
            for (int j = 0; j < 8; j++)
                S->sred[gw][wl][lane * 8 + j] = sa[j];
            if (lane == 0) S->zred[gw][wl] = z;
        }
        __syncthreads();

        // finalize + squash: one warp per g
        if (warp < kG && lane < 16) {
            const int g = warp;
            const float Z   = S->zred[g][0] + S->zred[g][1];
            const float num = S->sred[g][0][lane] + S->sred[g][1][lane];
            const float s = num / Z;
            float sq = s * s;
            #pragma unroll
            for (int off = 8; off; off >>= 1)
                sq += __shfl_xor_sync(0x0000ffffu, sq, off);
            const float coef = sqrtf(sq) / (1.f + sq);
            const float vnew = s * coef;
            if (last) {
                out[(size_t)(b0 + g) * (kO * kNC) + (size_t)lane * kNC + c] = vnew;
            } else {
                S->v[g][lane] += vnew;              // vacc = v0 + v1 (linearity)
            }
        }
        if (!last) __syncthreads();
    }
}

extern "C" void kernel_launch(void* const* d_in, const int* in_sizes, int n_in,
                              void* d_out, int out_size) {
    const float* x = (const float*)d_in[0];            // [64, 8, 800]
    const float* W = (const float*)d_in[1];            // [128, 800, 8, 16]
    float* out = (float*)d_out;                        // [64, 16, 128]

    transpose_x_kernel<<<(kB * kR + kT - 1) / kT, kT>>>(x);

    static_assert(sizeof(Smem) <= 227 * 1024, "smem budget");
    cudaFuncSetAttribute(caps_route_kernel,
                         cudaFuncAttributeMaxDynamicSharedMemorySize,
                         (int)sizeof(Smem));
    caps_route_kernel<<<kNC * kBPC, kT, sizeof(Smem)>>>(W, out);
}

// round 16
// speedup vs baseline: 1.1980x; 1.0619x over previous
#include <cuda_runtime.h>
#include <cuda_fp16.h>

// CapsuleLayer dynamic routing, round 15: two kernels, G=8.
// x: [B=64, Cin=8, R=800] fp32 ; W: [NC=128, R=800, Cin=8, O=16] fp32
// out: [B=64, O=16, NC=128] fp32
//
// R15 = R14 with the NaN bug fixed: the a2 butterfly stage read
// uninitialized a2[0] ("a2[0]*0.f + a4[j]" editing slip); now plain
// a4[j]. Structure: R11 phase 1 (proven) + lane-per-r phase 2
// (full dot in-lane, exp once per r, 16-SHFL halving reduction).

namespace {

constexpr int kB    = 64;
constexpr int kCin  = 8;
constexpr int kR    = 800;
constexpr int kNC   = 128;
constexpr int kO    = 16;
constexpr int kG    = 8;
constexpr int kT    = 512;
constexpr int kBPC  = kB / kG;        // 8 CTAs per capsule
constexpr int kWRow = kCin * kO;

struct Smem {
    __half2 prio[kG][kR][kO / 2];     // 204800 B
    float   sred[kG][16][kO];         //   8192 B
    float   zred[kG][2];              //     64 B
    float   v[kG][kO];                //    512 B
};

// exp(x) entirely on fma/alu pipes. Valid for |x| < ~88 (inputs bounded ~50).
__device__ __forceinline__ float fast_exp(float x) {
    const float t  = fmaf(x, 1.44269504f, 12582912.0f);
    const float fi = t - 12582912.0f;
    const float f  = fmaf(x, 1.44269504f, -fi);
    float p = 1.54035304e-4f;
    p = fmaf(p, f, 1.33335581e-3f);
    p = fmaf(p, f, 9.61812911e-3f);
    p = fmaf(p, f, 5.55041087e-2f);
    p = fmaf(p, f, 2.40226507e-1f);
    p = fmaf(p, f, 6.93147182e-1f);
    p = fmaf(p, f, 1.0f);
    const int ii = __float_as_int(t) - 0x4B400000;
    return __int_as_float(__float_as_int(p) + (ii << 23));
}

} // namespace

// fp16 transposed x: xT[b][r][i], 16B rows. 819200 B scratch.
__device__ __align__(128) static __half d_xT[kB * kR * kCin];

__global__ void transpose_x_kernel(const float* __restrict__ x) {
    const int id = blockIdx.x * blockDim.x + threadIdx.x;   // one (b, r) each
    if (id >= kB * kR) return;
    const int b = id / kR;
    const int r = id - b * kR;
    const float* src = x + (size_t)b * (kCin * kR) + r;
    union { __half2 h[4]; uint4 u; } cv;
    #pragma unroll
    for (int k = 0; k < 4; k++)
        cv.h[k] = __floats2half2_rn(src[(2 * k) * kR], src[(2 * k + 1) * kR]);
    *reinterpret_cast<uint4*>(&d_xT[(size_t)id * kCin]) = cv.u;
}

__global__ __launch_bounds__(kT, 1)
void caps_route_kernel(const float* __restrict__ W,
                       float* __restrict__ out) {
    extern __shared__ char smem_raw[];
    Smem* S = reinterpret_cast<Smem*>(smem_raw);

    const int t    = threadIdx.x;
    const int lane = t & 31;
    const int warp = t >> 5;
    const int c    = blockIdx.x / kBPC;
    const int b0   = (blockIdx.x % kBPC) * kG;
    const float* Wc = W + (size_t)c * (kR * kWRow);
    const __half* xT = d_xT + (size_t)b0 * (kR * kCin);

    // ---- phase 1: priors + fused uniform (pass-0) sums ----
    // lane = (rr:3 | oq:2). W held in regs per group; g in two 4-g halves.
    {
        const int oq = lane & 3;
        const int rr = lane >> 2;
        float ss[kG][4];
        #pragma unroll
        for (int g = 0; g < kG; g++)
            #pragma unroll
            for (int j = 0; j < 4; j++) ss[g][j] = 0.f;

        for (int grp = warp; grp < kR / 8; grp += kT / 32) {
            const int r = grp * 8 + rr;
            const float4* wr = reinterpret_cast<const float4*>(Wc + (size_t)r * kWRow) + oq;
            float4 w[kCin];
            #pragma unroll
            for (int i = 0; i < kCin; i++) w[i] = __ldg(wr + i * 4);

            #pragma unroll
            for (int gh = 0; gh < 2; gh++) {
                union { uint4 u; __half2 h[4]; } xa[4];
                #pragma unroll
                for (int gg = 0; gg < 4; gg++)
                    xa[gg].u = *reinterpret_cast<const uint4*>(
                        xT + ((size_t)(gh * 4 + gg) * kR + r) * kCin);

                #pragma unroll
                for (int gg = 0; gg < 4; gg++) {
                    const int g = gh * 4 + gg;
                    float xv[8];
                    #pragma unroll
                    for (int k = 0; k < 4; k++) {
                        const float2 f = __half22float2(xa[gg].h[k]);
                        xv[2 * k] = f.x; xv[2 * k + 1] = f.y;
                    }
                    float4 acc = make_float4(0.f, 0.f, 0.f, 0.f);
                    #pragma unroll
                    for (int i = 0; i < kCin; i++) {
                        acc.x = fmaf(w[i].x, xv[i], acc.x);
                        acc.y = fmaf(w[i].y, xv[i], acc.y);
                        acc.z = fmaf(w[i].z, xv[i], acc.z);
                        acc.w = fmaf(w[i].w, xv[i], acc.w);
                    }
                    union { __half2 h[2]; uint2 u; } pv;
                    pv.h[0] = __floats2half2_rn(acc.x, acc.y);
                    pv.h[1] = __floats2half2_rn(acc.z, acc.w);
                    *reinterpret_cast<uint2*>(&S->prio[g][r][oq * 2]) = pv.u;
                    ss[g][0] += acc.x; ss[g][1] += acc.y;
                    ss[g][2] += acc.z; ss[g][3] += acc.w;
                }
            }
        }
        // reduce ss over rr (lane bits 2..4); lanes rr==0 store per-warp partials
        #pragma unroll
        for (int s = 4; s <= 16; s <<= 1)
            #pragma unroll
            for (int g = 0; g < kG; g++)
                #pragma unroll
                for (int j = 0; j < 4; j++)
                    ss[g][j] += __shfl_xor_sync(0xffffffffu, ss[g][j], s);
        if (rr == 0) {
            #pragma unroll
            for (int g = 0; g < kG; g++)
                *reinterpret_cast<float4*>(&S->sred[g][warp][oq * 4]) =
                    make_float4(ss[g][0], ss[g][1], ss[g][2], ss[g][3]);
        }
    }
    __syncthreads();

    // ---- pass-0 finalize: v0 = squash(sum / R), one warp per g ----
    if (warp < kG && lane < 16) {
        float s = 0.f;
        #pragma unroll
        for (int w = 0; w < 16; w++) s += S->sred[warp][w][lane];
        s *= (1.f / kR);
        float sq = s * s;
        #pragma unroll
        for (int off = 8; off; off >>= 1)
            sq += __shfl_xor_sync(0x0000ffffu, sq, off);
        const float coef = sqrtf(sq) / (1.f + sq);
        S->v[warp][lane] = s * coef;
    }
    __syncthreads();

    // ---- routing: 2 exp-weighted passes, lane-per-r ----
    // 2 warps per g: gw = warp>>1, wl = warp&1. lane owns full row r.
    const int gw = warp >> 1;
    const int wl = warp & 1;

    #pragma unroll
    for (int pass = 0; pass < 2; pass++) {
        const bool last = (pass == 1);

        float vv[16];
        #pragma unroll
        for (int j = 0; j < 16; j++) vv[j] = S->v[gw][j];

        float z = 0.f, sa[16];
        #pragma unroll
        for (int j = 0; j < 16; j++) sa[j] = 0.f;

        for (int rb = wl * 32; rb < kR; rb += 64) {
            const int r = rb + lane;
            const uint4* rowp = reinterpret_cast<const uint4*>(&S->prio[gw][r][0]);
            union { uint4 u; __half2 h[4]; } c0, c1;
            c0.u = rowp[0];
            c1.u = rowp[1];
            float p[16];
            #pragma unroll
            for (int k = 0; k < 4; k++) {
                float2 f = __half22float2(c0.h[k]);
                p[2 * k] = f.x; p[2 * k + 1] = f.y;
                f = __half22float2(c1.h[k]);
                p[8 + 2 * k] = f.x; p[8 + 2 * k + 1] = f.y;
            }
            float d = 0.f;
            #pragma unroll
            for (int j = 0; j < 16; j++) d = fmaf(p[j], vv[j], d);
            const float e = fast_exp(d);        // logits bounded: |d| < ~50
            z += e;
            #pragma unroll
            for (int j = 0; j < 16; j++) sa[j] = fmaf(e, p[j], sa[j]);
        }

        // halving butterfly: 16 o-values over 32 lanes in 16 SHFL.
        // Each stage: keep the half this lane owns, exchange the other.
        float a8[8];
        {
            const bool hi = (lane & 16) != 0;
            #pragma unroll
            for (int j = 0; j < 8; j++) {
                const float send = hi ? sa[j] : sa[j + 8];
                const float keep = hi ? sa[j + 8] : sa[j];
                a8[j] = keep + __shfl_xor_sync(0xffffffffu, send, 16);
            }
        }
        float a4[4];
        {
            const bool hi = (lane & 8) != 0;
            #pragma unroll
            for (int j = 0; j < 4; j++) {
                const float send = hi ? a8[j] : a8[j + 4];
                const float keep = hi ? a8[j + 4] : a8[j];
                a4[j] = keep + __shfl_xor_sync(0xffffffffu, send, 8);
            }
        }
        float a2[2];
        {
            const bool hi = (lane & 4) != 0;
            #pragma unroll
            for (int j = 0; j < 2; j++) {
                const float send = hi ? a4[j] : a4[j + 2];
                const float keep = hi ? a4[j + 2] : a4[j];
                a2[j] = keep + __shfl_xor_sync(0xffffffffu, send, 4);
            }
        }
        float a1;
        {
            const bool hi = (lane & 2) != 0;
            const float send = hi ? a2[0] : a2[1];
            const float keep = hi ? a2[1] : a2[0];
            a1 = keep + __shfl_xor_sync(0xffffffffu, send, 2);
        }
        a1 += __shfl_xor_sync(0xffffffffu, a1, 1);
        // z full butterfly
        #pragma unroll
        for (int s = 16; s >= 1; s >>= 1)
            z += __shfl_xor_sync(0xffffffffu, z, s);

        const int own = ((lane >> 4) & 1) * 8 + ((lane >> 3) & 1) * 4 +
                        ((lane >> 2) & 1) * 2 + ((lane >> 1) & 1);
        if ((lane & 1) == 0) S->sred[gw][wl][own] = a1;
        if (lane == 0) S->zred[gw][wl] = z;
        __syncthreads();

        // finalize + squash: one warp per g
        if (warp < kG && lane < 16) {
            const int g = warp;
            const float Z   = S->zred[g][0] + S->zred[g][1];
            const float num = S->sred[g][0][lane] + S->sred[g][1][lane];
            const float s = num / Z;
            float sq = s * s;
            #pragma unroll
            for (int off = 8; off; off >>= 1)
                sq += __shfl_xor_sync(0x0000ffffu, sq, off);
            const float coef = sqrtf(sq) / (1.f + sq);
            const float vnew = s * coef;
            if (last) {
                out[(size_t)(b0 + g) * (kO * kNC) + (size_t)lane * kNC + c] = vnew;
            } else {
                S->v[g][lane] += vnew;              // vacc = v0 + v1 (linearity)
            }
        }
        if (!last) __syncthreads();
    }
}

extern "C" void kernel_launch(void* const* d_in, const int* in_sizes, int n_in,
                              void* d_out, int out_size) {
    const float* x = (const float*)d_in[0];            // [64, 8, 800]
    const float* W = (const float*)d_in[1];            // [128, 800, 8, 16]
    float* out = (float*)d_out;                        // [64, 16, 128]

    transpose_x_kernel<<<(kB * kR + kT - 1) / kT, kT>>>(x);

    static_assert(sizeof(Smem) <= 227 * 1024, "smem budget");
    cudaFuncSetAttribute(caps_route_kernel,
                         cudaFuncAttributeMaxDynamicSharedMemorySize,
                         (int)sizeof(Smem));
    caps_route_kernel<<<kNC * kBPC, kT, sizeof(Smem)>>>(W, out);
}